// round 12
// baseline (speedup 1.0000x reference)
#include <cuda_runtime.h>
#include <cuda_bf16.h>
#include <math.h>
#include <stdint.h>

// Problem constants
#define B_ 2
#define T_ 2048
#define C_ 2048
#define H_ 16
#define HS_ 128
#define AL_ 10
#define KDIM 2048
#define M_ROWS 4096

#define NEG_BIG (-1e30f)

// ---------------- scratch: split-bf16 tensors ----------------
#define QKV_ELEMS (B_*H_*T_*HS_)
__device__ __nv_bfloat16 g_Qh[QKV_ELEMS], g_Ql[QKV_ELEMS];
__device__ __nv_bfloat16 g_Kh[QKV_ELEMS], g_Kl[QKV_ELEMS];
__device__ __nv_bfloat16 g_Vh[QKV_ELEMS], g_Vl[QKV_ELEMS];
__device__ __nv_bfloat16 g_Yh[M_ROWS*C_], g_Yl[M_ROWS*C_];
__device__ __nv_bfloat16 g_xh[M_ROWS*KDIM], g_xl[M_ROWS*KDIM];
__device__ __nv_bfloat16 g_wah[3*C_*KDIM], g_wal[3*C_*KDIM];
__device__ __nv_bfloat16 g_wph[C_*KDIM], g_wpl[C_*KDIM];
__device__ float g_AK[H_*AL_*HS_];
__device__ float g_AV[H_*AL_*HS_];

// ======================= helpers =======================
__device__ __forceinline__ uint32_t smem_u32(const void* p) {
    uint32_t a;
    asm("{ .reg .u64 t; cvta.to.shared.u64 t, %1; cvt.u32.u64 %0, t; }" : "=r"(a) : "l"(p));
    return a;
}

#define LDSM_X4(r, addr) \
    asm volatile("ldmatrix.sync.aligned.m8n8.x4.shared.b16 {%0,%1,%2,%3}, [%4];" \
        : "=r"((r)[0]), "=r"((r)[1]), "=r"((r)[2]), "=r"((r)[3]) : "r"(addr))

#define LDSM_X4_T(r, addr) \
    asm volatile("ldmatrix.sync.aligned.m8n8.x4.trans.shared.b16 {%0,%1,%2,%3}, [%4];" \
        : "=r"((r)[0]), "=r"((r)[1]), "=r"((r)[2]), "=r"((r)[3]) : "r"(addr))

#define MMA_BF16(d, a, b0, b1) \
    asm volatile("mma.sync.aligned.m16n8k16.row.col.f32.bf16.bf16.f32 " \
        "{%0,%1,%2,%3}, {%4,%5,%6,%7}, {%8,%9}, {%0,%1,%2,%3};" \
        : "+f"((d)[0]), "+f"((d)[1]), "+f"((d)[2]), "+f"((d)[3]) \
        : "r"((a)[0]), "r"((a)[1]), "r"((a)[2]), "r"((a)[3]), "r"(b0), "r"(b1))

#define CP_A16(dst, src) \
    asm volatile("cp.async.cg.shared.global [%0], [%1], 16;" :: "r"(dst), "l"(src))
#define CP_COMMIT() asm volatile("cp.async.commit_group;")
#define CP_WAIT(n)  asm volatile("cp.async.wait_group %0;" :: "n"(n))

// swizzled byte offset inside a [rows][64B] bf16 tile (4x 16B chunks/row)
__device__ __forceinline__ uint32_t tswz(int row, int chunk) {
    return (uint32_t)(row * 64 + ((chunk ^ ((row >> 1) & 3)) << 4));
}

__device__ __forceinline__ void pack2(float a, float b, uint32_t& hi, uint32_t& lo) {
    __nv_bfloat162 th = __floats2bfloat162_rn(a, b);
    __nv_bfloat162 tl = __floats2bfloat162_rn(a - __low2float(th), b - __high2float(th));
    hi = *reinterpret_cast<uint32_t*>(&th);
    lo = *reinterpret_cast<uint32_t*>(&tl);
}

// ======================================================================
// prep: fp32 -> bf16 hi/lo split (elementwise)
// ======================================================================
__global__ __launch_bounds__(256) void conv_split(
    const float4* __restrict__ src, uint2* __restrict__ hi,
    uint2* __restrict__ lo, int n4)
{
    const int i = blockIdx.x * blockDim.x + threadIdx.x;
    if (i >= n4) return;
    const float4 v = src[i];
    uint32_t h0, l0, h1, l1;
    pack2(v.x, v.y, h0, l0);
    pack2(v.z, v.w, h1, l1);
    hi[i] = make_uint2(h0, h1);
    lo[i] = make_uint2(l0, l1);
}

// ======================================================================
// Adapter K/V block body (fused into tgemm<0> launch).
// abx in [0,4096): output column np = 2048 + abx of adapter_emb @ W_attn.T
// ======================================================================
__device__ void adapter_kv_block(const float* __restrict__ W,
                                 const float* __restrict__ emb, int abx)
{
    const int np = 2048 + abx;
    const float* wrow = W + (long)np * KDIM;

    float part[AL_] = {};
    for (int k = threadIdx.x; k < KDIM; k += 128) {
        float w = wrow[k];
        #pragma unroll
        for (int j = 0; j < AL_; j++) part[j] += w * emb[j*KDIM + k];
    }
    #pragma unroll
    for (int j = 0; j < AL_; j++)
        #pragma unroll
        for (int off = 16; off; off >>= 1)
            part[j] += __shfl_xor_sync(0xffffffffu, part[j], off);

    __shared__ float red[AL_][4];
    const int w = threadIdx.x >> 5, lane = threadIdx.x & 31;
    if (lane == 0)
        #pragma unroll
        for (int j = 0; j < AL_; j++) red[j][w] = part[j];
    __syncthreads();
    if (threadIdx.x < AL_) {
        const int j = threadIdx.x;
        float s = red[j][0] + red[j][1] + red[j][2] + red[j][3];
        const int isv = abx >> 11;
        const int nn  = abx & 2047;
        const int h   = nn >> 7, d = nn & 127;
        float* dst = isv ? g_AV : g_AK;
        dst[(h*AL_ + j)*HS_ + d] = s;
    }
}

// ======================================================================
// split-bf16 x3 GEMM (NT): CTA 128x128, 4 warps of 64x64, KC=32,
// 3-stage cp.async pipeline, 2 CTAs/SM.
// MODE 0: rope + pack -> g_{Q,K,V}{h,l}; blocks bx>=48 run adapter_kv.
// MODE 1: fp32 write to Cout.
// ======================================================================
#define KC 32
#define STAGE_B 32768
#define NSTAGE 3
#define GEMM_SMEM (NSTAGE*STAGE_B)   // 96 KB -> 2 CTAs/SM

template<int MODE>
__global__ __launch_bounds__(128, 2) void tgemm(
    const __nv_bfloat16* __restrict__ Ah, const __nv_bfloat16* __restrict__ Al,
    const __nv_bfloat16* __restrict__ Bh, const __nv_bfloat16* __restrict__ Bl,
    const float* __restrict__ rope, float* __restrict__ Cout,
    const float* __restrict__ Wfp, const float* __restrict__ emb)
{
    if (MODE == 0 && blockIdx.x >= 48) {
        adapter_kv_block(Wfp, emb, (blockIdx.x - 48) * 32 + blockIdx.y);
        return;
    }

    extern __shared__ __align__(1024) char smx[];
    const uint32_t sb = smem_u32(smx);

    const int tid  = threadIdx.x;
    const int wid  = tid >> 5;
    const int lane = tid & 31;
    const int wm   = wid & 1;
    const int wn   = wid >> 1;
    const int bm   = blockIdx.y << 7;
    const int bn   = blockIdx.x << 7;

    int lrow[4], lchk[4]; uint32_t lsw[4];
    #pragma unroll
    for (int f = 0; f < 4; f++) {
        int idx = tid + (f << 7);
        lrow[f] = idx >> 2; lchk[f] = idx & 3;
        lsw[f] = tswz(lrow[f], lchk[f]);
    }

    const int grp = lane >> 3, lr = lane & 7;
    uint32_t offA[4][2], offB[4][2];
    #pragma unroll
    for (int i = 0; i < 4; i++)
        #pragma unroll
        for (int ks = 0; ks < 2; ks++) {
            int row = wm*64 + i*16 + (grp & 1)*8 + lr;
            offA[i][ks] = tswz(row, (grp >> 1) + 2*ks);
        }
    #pragma unroll
    for (int jj = 0; jj < 4; jj++)
        #pragma unroll
        for (int ks = 0; ks < 2; ks++) {
            int row = wn*64 + jj*16 + (grp >> 1)*8 + lr;
            offB[jj][ks] = tswz(row, (grp & 1) + 2*ks);
        }

    float acc[4][8][4];
    #pragma unroll
    for (int i = 0; i < 4; i++)
        #pragma unroll
        for (int j = 0; j < 8; j++)
            #pragma unroll
            for (int c = 0; c < 4; c++) acc[i][j][c] = 0.f;

    const __nv_bfloat16* Abh = Ah + (long)bm * KDIM;
    const __nv_bfloat16* Abl = Al + (long)bm * KDIM;
    const __nv_bfloat16* Bbh = Bh + (long)bn * KDIM;
    const __nv_bfloat16* Bbl = Bl + (long)bn * KDIM;

    auto load_stage = [&](int c, int s) {
        const uint32_t st = sb + (uint32_t)s * STAGE_B;
        const long kb = (long)c * KC;
        #pragma unroll
        for (int f = 0; f < 4; f++) {
            const long ga = (long)lrow[f]*KDIM + kb + lchk[f]*8;
            CP_A16(st + 0*8192 + lsw[f], Abh + ga);
            CP_A16(st + 1*8192 + lsw[f], Abl + ga);
            CP_A16(st + 2*8192 + lsw[f], Bbh + ga);
            CP_A16(st + 3*8192 + lsw[f], Bbl + ga);
        }
        CP_COMMIT();
    };

    const int NCH = KDIM / KC;     // 64
    load_stage(0, 0);
    load_stage(1, 1);

    for (int c = 0; c < NCH; c++) {
        CP_WAIT(1);
        __syncthreads();

        const uint32_t stg = sb + (uint32_t)(c % NSTAGE) * STAGE_B;
        #pragma unroll
        for (int ks = 0; ks < 2; ks++) {
            uint32_t ah[4][4], al[4][4], bh[4][4], bl[4][4];
            #pragma unroll
            for (int i = 0; i < 4; i++) {
                LDSM_X4(ah[i], stg + 0*8192 + offA[i][ks]);
                LDSM_X4(al[i], stg + 1*8192 + offA[i][ks]);
            }
            #pragma unroll
            for (int jj = 0; jj < 4; jj++) {
                LDSM_X4(bh[jj], stg + 2*8192 + offB[jj][ks]);
                LDSM_X4(bl[jj], stg + 3*8192 + offB[jj][ks]);
            }
            #pragma unroll
            for (int i = 0; i < 4; i++)
                #pragma unroll
                for (int j = 0; j < 8; j++) {
                    const int jj = j >> 1, jo = (j & 1) << 1;
                    MMA_BF16(acc[i][j], ah[i], bh[jj][jo], bh[jj][jo+1]);
                    MMA_BF16(acc[i][j], ah[i], bl[jj][jo], bl[jj][jo+1]);
                    MMA_BF16(acc[i][j], al[i], bh[jj][jo], bh[jj][jo+1]);
                }
        }

        if (c + 2 < NCH) load_stage(c + 2, (c + 2) % NSTAGE);
        else CP_COMMIT();
    }

    // ---------------- epilogue ----------------
    const int lr4 = lane >> 2;
    const int lc2 = (lane & 3) << 1;

    if (MODE == 0) {
        const int sel = bn >> 11;
        const int hh  = (bn & 2047) >> 7;
        __nv_bfloat16* baseH = (sel == 0 ? g_Qh : (sel == 1 ? g_Kh : g_Vh));
        __nv_bfloat16* baseL = (sel == 0 ? g_Ql : (sel == 1 ? g_Kl : g_Vl));
        #pragma unroll
        for (int i = 0; i < 4; i++) {
            #pragma unroll
            for (int j = 0; j < 8; j++) {
                const int d = wn*64 + j*8 + lc2;
                #pragma unroll
                for (int rh = 0; rh < 2; rh++) {
                    const int m = bm + wm*64 + i*16 + lr4 + rh*8;
                    const int b = m >> 11, t = m & 2047;
                    float v0 = acc[i][j][rh*2], v1 = acc[i][j][rh*2+1];
                    if (sel < 2) {
                        const float2 rr = *(const float2*)(rope + (long)t*128 + d);
                        const float o0 = v0*rr.x - v1*rr.y;
                        const float o1 = v1*rr.x + v0*rr.y;
                        v0 = o0; v1 = o1;
                    }
                    uint32_t hi, lo; pack2(v0, v1, hi, lo);
                    const long idx = ((long)(b*H_ + hh)*T_ + t)*HS_ + d;
                    *(uint32_t*)((uint16_t*)baseH + idx) = hi;
                    *(uint32_t*)((uint16_t*)baseL + idx) = lo;
                }
            }
        }
    } else {
        #pragma unroll
        for (int i = 0; i < 4; i++)
            #pragma unroll
            for (int j = 0; j < 8; j++) {
                const int ncol = bn + wn*64 + j*8 + lc2;
                #pragma unroll
                for (int rh = 0; rh < 2; rh++) {
                    const int m = bm + wm*64 + i*16 + lr4 + rh*8;
                    *(float2*)(Cout + (long)m*C_ + ncol) =
                        make_float2(acc[i][j][rh*2], acc[i][j][rh*2+1]);
                }
            }
    }
}

// ======================================================================
// Flash attention (split-bf16 x3 tensor cores), cp.async loads of
// pre-split Q/K/V, 2-stage KV pipeline, fused adapter + gating.
// BM=128, BN=64, 8 warps.  (round-9 version — best known)
// ======================================================================
#define FQHI 0
#define FQLO 32768
#define FKV  65536
#define KVSTAGE_B 65536          // Kh,Kl,Vh,Vl x 16KB
#define FAK  (FKV + 2*KVSTAGE_B)             // 196608
#define FAV  (FAK + AL_*HS_*4)               // 201728
#define FLASH_SMEM (FAV + AL_*HS_*4)         // 206848

__global__ __launch_bounds__(256, 1) void flash_mma(const float* __restrict__ gating)
{
    extern __shared__ __align__(1024) char fsm[];
    const uint32_t sb = smem_u32(fsm);

    const int tid  = threadIdx.x;
    const int w    = tid >> 5;
    const int lane = tid & 31;
    const int grp  = lane >> 3, lr = lane & 7;
    const int lam  = lane & 3;
    const int rsub = lane >> 2;

    const int qb = (gridDim.x - 1) - blockIdx.x;
    const int bhI = blockIdx.y;
    const int h  = bhI & 15;
    const int b  = bhI >> 4;

    const __nv_bfloat16* Qhg = g_Qh + (long)bhI*T_*HS_ + (long)qb*128*HS_;
    const __nv_bfloat16* Qlg = g_Ql + (long)bhI*T_*HS_ + (long)qb*128*HS_;
    const __nv_bfloat16* Khg = g_Kh + (long)bhI*T_*HS_;
    const __nv_bfloat16* Klg = g_Kl + (long)bhI*T_*HS_;
    const __nv_bfloat16* Vhg = g_Vh + (long)bhI*T_*HS_;
    const __nv_bfloat16* Vlg = g_Vl + (long)bhI*T_*HS_;

    // ---- group 0: Q tiles (hi+lo) ----
    #pragma unroll
    for (int f = 0; f < 8; f++) {
        const int slot = tid + (f << 8);           // 0..2047
        const int row = slot >> 4, c8 = slot & 15;
        const uint32_t off = (uint32_t)((c8 >> 2) * 8192) + tswz(row, c8 & 3);
        const long g = (long)row*HS_ + c8*8;
        CP_A16(sb + FQHI + off, Qhg + g);
        CP_A16(sb + FQLO + off, Qlg + g);
    }
    CP_COMMIT();

    auto load_kv = [&](int kb) {
        const uint32_t st = sb + FKV + (uint32_t)(kb & 1) * KVSTAGE_B;
        const long gb = (long)kb*64*HS_;
        #pragma unroll
        for (int f = 0; f < 4; f++) {
            const int slot = tid + (f << 8);       // 0..1023
            const int row = slot >> 4, c8 = slot & 15;
            const uint32_t off = (uint32_t)((c8 >> 2) * 4096) + tswz(row, c8 & 3);
            const long g = gb + (long)row*HS_ + c8*8;
            CP_A16(st + 0     + off, Khg + g);
            CP_A16(st + 16384 + off, Klg + g);
            CP_A16(st + 32768 + off, Vhg + g);
            CP_A16(st + 49152 + off, Vlg + g);
        }
        CP_COMMIT();
    };

    // ---- adapter tiles (fp32, plain stores) ----
    {
        const float4* AKg = (const float4*)(g_AK + h*AL_*HS_);
        const float4* AVg = (const float4*)(g_AV + h*AL_*HS_);
        for (int i = tid; i < AL_*HS_/4; i += 256) {
            ((float4*)(fsm + FAK))[i] = AKg[i];
            ((float4*)(fsm + FAV))[i] = AVg[i];
        }
    }

    float O[16][4];
    #pragma unroll
    for (int nf = 0; nf < 16; nf++)
        #pragma unroll
        for (int c = 0; c < 4; c++) O[nf][c] = 0.f;
    float m0 = NEG_BIG, m1 = NEG_BIG, l0 = 0.f, l1 = 0.f;
    const float scale = 0.08838834764831843f;

    const int rowg0 = qb*128 + 16*w + rsub;
    const int warp_rmax = qb*128 + 16*w + 15;

    const int kmax = 2*qb + 2;
    load_kv(0);                                   // group 1

    for (int kb = 0; kb < kmax; kb++) {
        if (kb + 1 < kmax) load_kv(kb + 1);
        else CP_COMMIT();
        CP_WAIT(1);
        __syncthreads();

        if (kb*64 <= warp_rmax) {
            const uint32_t kvst = sb + FKV + (uint32_t)(kb & 1) * KVSTAGE_B;

            // ---- S = Q K^T ----
            float S[8][4];
            #pragma unroll
            for (int j = 0; j < 8; j++)
                #pragma unroll
                for (int c = 0; c < 4; c++) S[j][c] = 0.f;

            #pragma unroll
            for (int ks = 0; ks < 8; ks++) {
                const int tQ = ks >> 1, chb = (ks & 1) << 1;
                const int arow = 16*w + (grp & 1)*8 + lr;
                const uint32_t aoff = (uint32_t)(tQ*8192) + tswz(arow, chb + (grp >> 1));
                uint32_t ah[4], al[4];
                LDSM_X4(ah, sb + FQHI + aoff);
                LDSM_X4(al, sb + FQLO + aoff);
                #pragma unroll
                for (int jj = 0; jj < 4; jj++) {
                    const int brow = jj*16 + (grp >> 1)*8 + lr;
                    const uint32_t boff = (uint32_t)(tQ*4096) + tswz(brow, (grp & 1) + chb);
                    uint32_t kh[4], kl[4];
                    LDSM_X4(kh, kvst + 0     + boff);
                    LDSM_X4(kl, kvst + 16384 + boff);
                    #pragma unroll
                    for (int j2 = 0; j2 < 2; j2++) {
                        const int j = jj*2 + j2, jo = j2 << 1;
                        MMA_BF16(S[j], ah, kh[jo], kh[jo+1]);
                        MMA_BF16(S[j], ah, kl[jo], kl[jo+1]);
                        MMA_BF16(S[j], al, kh[jo], kh[jo+1]);
                    }
                }
            }

            // ---- scale + mask ----
            const bool needMask = (kb*64 + 63) > (qb*128 + 16*w);
            #pragma unroll
            for (int j = 0; j < 8; j++)
                #pragma unroll
                for (int c = 0; c < 4; c++) {
                    float sv = S[j][c] * scale;
                    if (needMask) {
                        const int colg = kb*64 + j*8 + 2*lam + (c & 1);
                        const int rowg = rowg0 + ((c >> 1) << 3);
                        if (colg > rowg) sv = NEG_BIG;
                    }
                    S[j][c] = sv;
                }

            // ---- online softmax ----
            float mx0 = S[0][0], mx1 = S[0][2];
            #pragma unroll
            for (int j = 0; j < 8; j++) {
                mx0 = fmaxf(mx0, fmaxf(S[j][0], S[j][1]));
                mx1 = fmaxf(mx1, fmaxf(S[j][2], S[j][3]));
            }
            mx0 = fmaxf(mx0, __shfl_xor_sync(0xffffffffu, mx0, 1));
            mx0 = fmaxf(mx0, __shfl_xor_sync(0xffffffffu, mx0, 2));
            mx1 = fmaxf(mx1, __shfl_xor_sync(0xffffffffu, mx1, 1));
            mx1 = fmaxf(mx1, __shfl_xor_sync(0xffffffffu, mx1, 2));
            const float mn0 = fmaxf(m0, mx0);
            const float mn1 = fmaxf(m1, mx1);
            const float corr0 = __expf(m0 - mn0);
            const float corr1 = __expf(m1 - mn1);
            float rs0 = 0.f, rs1 = 0.f;
            #pragma unroll
            for (int j = 0; j < 8; j++) {
                S[j][0] = __expf(S[j][0] - mn0);
                S[j][1] = __expf(S[j][1] - mn0);
                S[j][2] = __expf(S[j][2] - mn1);
                S[j][3] = __expf(S[j][3] - mn1);
                rs0 += S[j][0] + S[j][1];
                rs1 += S[j][2] + S[j][3];
            }
            l0 = l0*corr0 + rs0;
            l1 = l1*corr1 + rs1;
            m0 = mn0; m1 = mn1;
            #pragma unroll
            for (int nf = 0; nf < 16; nf++) {
                O[nf][0] *= corr0; O[nf][1] *= corr0;
                O[nf][2] *= corr1; O[nf][3] *= corr1;
            }

            // ---- O += P V ----
            #pragma unroll
            for (int ks2 = 0; ks2 < 4; ks2++) {
                const int j0 = 2*ks2, j1 = j0 + 1;
                uint32_t phi[4], plo[4];
                pack2(S[j0][0], S[j0][1], phi[0], plo[0]);
                pack2(S[j0][2], S[j0][3], phi[1], plo[1]);
                pack2(S[j1][0], S[j1][1], phi[2], plo[2]);
                pack2(S[j1][2], S[j1][3], phi[3], plo[3]);
                #pragma unroll
                for (int nc = 0; nc < 8; nc++) {
                    const int vrow = ks2*16 + (grp & 1)*8 + lr;
                    const uint32_t voff = (uint32_t)((nc >> 1) * 4096)
                                        + tswz(vrow, ((nc & 1) << 1) + (grp >> 1));
                    uint32_t vh[4], vl[4];
                    LDSM_X4_T(vh, kvst + 32768 + voff);
                    LDSM_X4_T(vl, kvst + 49152 + voff);
                    MMA_BF16(O[2*nc],   phi, vh[0], vh[1]);
                    MMA_BF16(O[2*nc+1], phi, vh[2], vh[3]);
                    MMA_BF16(O[2*nc],   phi, vl[0], vl[1]);
                    MMA_BF16(O[2*nc+1], phi, vl[2], vl[3]);
                    MMA_BF16(O[2*nc],   plo, vh[0], vh[1]);
                    MMA_BF16(O[2*nc+1], plo, vh[2], vh[3]);
                }
            }
        }
        __syncthreads();
    }

    // ---- finalize l ----
    l0 += __shfl_xor_sync(0xffffffffu, l0, 1);
    l0 += __shfl_xor_sync(0xffffffffu, l0, 2);
    l1 += __shfl_xor_sync(0xffffffffu, l1, 1);
    l1 += __shfl_xor_sync(0xffffffffu, l1, 2);

    // ---- adapter attention (q = hi+lo from smem) ----
    float sa0[AL_], sa1[AL_];
    #pragma unroll
    for (int j = 0; j < AL_; j++) { sa0[j] = 0.f; sa1[j] = 0.f; }
    const float* AKs = (const float*)(fsm + FAK);
    const float* AVs = (const float*)(fsm + FAV);
    #pragma unroll
    for (int rr = 0; rr < 2; rr++) {
        const int rowL = 16*w + rsub + rr*8;
        float* sa = rr ? sa1 : sa0;
        #pragma unroll
        for (int ch = 0; ch < 4; ch++) {
            const uint32_t off = (uint32_t)(lam * 8192) + tswz(rowL, ch);
            uint4 qh = *(const uint4*)(fsm + FQHI + off);
            uint4 ql = *(const uint4*)(fsm + FQLO + off);
            const uint32_t* qhp = (const uint32_t*)&qh;
            const uint32_t* qlp = (const uint32_t*)&ql;
            float q[8];
            #pragma unroll
            for (int e = 0; e < 4; e++) {
                __nv_bfloat162 bh2 = *reinterpret_cast<const __nv_bfloat162*>(&qhp[e]);
                __nv_bfloat162 bl2 = *reinterpret_cast<const __nv_bfloat162*>(&qlp[e]);
                q[2*e]   = __low2float(bh2)  + __low2float(bl2);
                q[2*e+1] = __high2float(bh2) + __high2float(bl2);
            }
            const int d0 = lam*32 + ch*8;
            #pragma unroll
            for (int j = 0; j < AL_; j++) {
                const float* ak = AKs + j*HS_ + d0;
                #pragma unroll
                for (int e = 0; e < 8; e++) sa[j] += q[e] * ak[e];
            }
        }
    }
    #pragma unroll
    for (int j = 0; j < AL_; j++) {
        sa0[j] += __shfl_xor_sync(0xffffffffu, sa0[j], 1);
        sa0[j] += __shfl_xor_sync(0xffffffffu, sa0[j], 2);
        sa1[j] += __shfl_xor_sync(0xffffffffu, sa1[j], 1);
        sa1[j] += __shfl_xor_sync(0xffffffffu, sa1[j], 2);
    }

    const float g = gating[h];
    #pragma unroll
    for (int rr = 0; rr < 2; rr++) {
        float* sa = rr ? sa1 : sa0;
        const float li = rr ? l1 : l0;
        const int rowg = rowg0 + rr*8;
        float mx = sa[0]*scale;
        #pragma unroll
        for (int j = 1; j < AL_; j++) mx = fmaxf(mx, sa[j]*scale);
        float pa[AL_], ssum = 0.f;
        #pragma unroll
        for (int j = 0; j < AL_; j++) { pa[j] = __expf(sa[j]*scale - mx); ssum += pa[j]; }
        const float pg = g / ssum;
        const float inv_l = 1.f / li;
        const long yidx0 = ((long)b*T_ + rowg)*C_ + h*HS_;
        #pragma unroll
        for (int nf = 0; nf < 16; nf++) {
            const int d = nf*8 + 2*lam;
            float o0 = O[nf][rr*2]   * inv_l;
            float o1 = O[nf][rr*2+1] * inv_l;
            #pragma unroll
            for (int j = 0; j < AL_; j++) {
                const float p = pa[j] * pg;
                o0 += p * AVs[j*HS_ + d];
                o1 += p * AVs[j*HS_ + d + 1];
            }
            uint32_t hi, lo; pack2(o0, o1, hi, lo);
            *(uint32_t*)((uint16_t*)g_Yh + yidx0 + d) = hi;
            *(uint32_t*)((uint16_t*)g_Yl + yidx0 + d) = lo;
        }
    }
}

// ======================================================================
extern "C" void kernel_launch(void* const* d_in, const int* in_sizes, int n_in,
                              void* d_out, int out_size)
{
    const float* x      = (const float*)d_in[0];
    const float* rope   = (const float*)d_in[1];
    const float* W_attn = (const float*)d_in[3];
    const float* W_proj = (const float*)d_in[4];
    const float* emb    = (const float*)d_in[5];
    const float* gating = (const float*)d_in[6];
    float* out = (float*)d_out;

    void *xh, *xl, *wah, *wal, *wph, *wpl, *yh, *yl;
    cudaGetSymbolAddress(&xh,  g_xh);  cudaGetSymbolAddress(&xl,  g_xl);
    cudaGetSymbolAddress(&wah, g_wah); cudaGetSymbolAddress(&wal, g_wal);
    cudaGetSymbolAddress(&wph, g_wph); cudaGetSymbolAddress(&wpl, g_wpl);
    cudaGetSymbolAddress(&yh,  g_Yh);  cudaGetSymbolAddress(&yl,  g_Yl);

    cudaFuncSetAttribute(tgemm<0>, cudaFuncAttributeMaxDynamicSharedMemorySize, GEMM_SMEM);
    cudaFuncSetAttribute(tgemm<1>, cudaFuncAttributeMaxDynamicSharedMemorySize, GEMM_SMEM);
    cudaFuncSetAttribute(flash_mma, cudaFuncAttributeMaxDynamicSharedMemorySize, FLASH_SMEM);

    // 0) split inputs into bf16 hi/lo
    {
        int n4;
        n4 = M_ROWS*KDIM/4;
        conv_split<<<(n4+255)/256, 256>>>((const float4*)x, (uint2*)xh, (uint2*)xl, n4);
        n4 = 3*C_*KDIM/4;
        conv_split<<<(n4+255)/256, 256>>>((const float4*)W_attn, (uint2*)wah, (uint2*)wal, n4);
        n4 = C_*KDIM/4;
        conv_split<<<(n4+255)/256, 256>>>((const float4*)W_proj, (uint2*)wph, (uint2*)wpl, n4);
    }
    // 1) QKV GEMM + rope -> split Q/K/V; adapter_kv fused in blocks bx>=48
    tgemm<0><<<dim3(48 + 128, 32), 128, GEMM_SMEM>>>(
        (const __nv_bfloat16*)xh, (const __nv_bfloat16*)xl,
        (const __nv_bfloat16*)wah, (const __nv_bfloat16*)wal, rope, nullptr,
        W_attn, emb);
    // 2) flash attention + fused adapter/gating -> split Y
    flash_mma<<<dim3(T_/128, B_*H_), 256, FLASH_SMEM>>>(gating);
    // 3) output projection -> fp32 out
    tgemm<1><<<dim3(16, 32), 128, GEMM_SMEM>>>(
        (const __nv_bfloat16*)yh, (const __nv_bfloat16*)yl,
        (const __nv_bfloat16*)wph, (const __nv_bfloat16*)wpl, nullptr, out,
        nullptr, nullptr);
}

// round 16
// speedup vs baseline: 1.0347x; 1.0347x over previous
#include <cuda_runtime.h>
#include <cuda_bf16.h>
#include <math.h>
#include <stdint.h>

// Problem constants
#define B_ 2
#define T_ 2048
#define C_ 2048
#define H_ 16
#define HS_ 128
#define AL_ 10
#define KDIM 2048
#define M_ROWS 4096

#define NEG_BIG (-1e30f)

// ---------------- scratch: split-bf16 tensors ----------------
#define QKV_ELEMS (B_*H_*T_*HS_)
__device__ __nv_bfloat16 g_Qh[QKV_ELEMS], g_Ql[QKV_ELEMS];
__device__ __nv_bfloat16 g_Kh[QKV_ELEMS], g_Kl[QKV_ELEMS];
__device__ __nv_bfloat16 g_Vh[QKV_ELEMS], g_Vl[QKV_ELEMS];
__device__ __nv_bfloat16 g_Yh[M_ROWS*C_], g_Yl[M_ROWS*C_];
__device__ __nv_bfloat16 g_xh[M_ROWS*KDIM], g_xl[M_ROWS*KDIM];
__device__ __nv_bfloat16 g_wah[3*C_*KDIM], g_wal[3*C_*KDIM];
__device__ __nv_bfloat16 g_wph[C_*KDIM], g_wpl[C_*KDIM];
__device__ float g_AK[H_*AL_*HS_];
__device__ float g_AV[H_*AL_*HS_];

// ======================= helpers =======================
__device__ __forceinline__ uint32_t smem_u32(const void* p) {
    uint32_t a;
    asm("{ .reg .u64 t; cvta.to.shared.u64 t, %1; cvt.u32.u64 %0, t; }" : "=r"(a) : "l"(p));
    return a;
}

#define LDSM_X4(r, addr) \
    asm volatile("ldmatrix.sync.aligned.m8n8.x4.shared.b16 {%0,%1,%2,%3}, [%4];" \
        : "=r"((r)[0]), "=r"((r)[1]), "=r"((r)[2]), "=r"((r)[3]) : "r"(addr))

#define LDSM_X4_T(r, addr) \
    asm volatile("ldmatrix.sync.aligned.m8n8.x4.trans.shared.b16 {%0,%1,%2,%3}, [%4];" \
        : "=r"((r)[0]), "=r"((r)[1]), "=r"((r)[2]), "=r"((r)[3]) : "r"(addr))

#define MMA_BF16(d, a, b0, b1) \
    asm volatile("mma.sync.aligned.m16n8k16.row.col.f32.bf16.bf16.f32 " \
        "{%0,%1,%2,%3}, {%4,%5,%6,%7}, {%8,%9}, {%0,%1,%2,%3};" \
        : "+f"((d)[0]), "+f"((d)[1]), "+f"((d)[2]), "+f"((d)[3]) \
        : "r"((a)[0]), "r"((a)[1]), "r"((a)[2]), "r"((a)[3]), "r"(b0), "r"(b1))

#define CP_A16(dst, src) \
    asm volatile("cp.async.cg.shared.global [%0], [%1], 16;" :: "r"(dst), "l"(src))
#define CP_COMMIT() asm volatile("cp.async.commit_group;")
#define CP_WAIT(n)  asm volatile("cp.async.wait_group %0;" :: "n"(n))

// swizzled byte offset inside a [rows][64B] bf16 tile (4x 16B chunks/row)
__device__ __forceinline__ uint32_t tswz(int row, int chunk) {
    return (uint32_t)(row * 64 + ((chunk ^ ((row >> 1) & 3)) << 4));
}

__device__ __forceinline__ void pack2(float a, float b, uint32_t& hi, uint32_t& lo) {
    __nv_bfloat162 th = __floats2bfloat162_rn(a, b);
    __nv_bfloat162 tl = __floats2bfloat162_rn(a - __low2float(th), b - __high2float(th));
    hi = *reinterpret_cast<uint32_t*>(&th);
    lo = *reinterpret_cast<uint32_t*>(&tl);
}

// ======================================================================
// prep: fp32 -> bf16 hi/lo split (elementwise)
// ======================================================================
__global__ __launch_bounds__(256) void conv_split(
    const float4* __restrict__ src, uint2* __restrict__ hi,
    uint2* __restrict__ lo, int n4)
{
    const int i = blockIdx.x * blockDim.x + threadIdx.x;
    if (i >= n4) return;
    const float4 v = src[i];
    uint32_t h0, l0, h1, l1;
    pack2(v.x, v.y, h0, l0);
    pack2(v.z, v.w, h1, l1);
    hi[i] = make_uint2(h0, h1);
    lo[i] = make_uint2(l0, l1);
}

// ======================================================================
// prep for W_attn WITH adapter K/V fused as extra blocks.
// blocks [0, n4blk)           : hi/lo split of W_attn
// blocks [n4blk, n4blk+4096)  : adapter column  (cheap resource envelope:
//                               no dynamic smem, low regs)
// ======================================================================
__global__ __launch_bounds__(256) void conv_split_wa(
    const float4* __restrict__ src, uint2* __restrict__ hi,
    uint2* __restrict__ lo, int n4,
    const float* __restrict__ Wfp, const float* __restrict__ emb)
{
    const int n4blk = (n4 + 255) >> 8;
    if ((int)blockIdx.x < n4blk) {
        const int i = blockIdx.x * 256 + threadIdx.x;
        if (i >= n4) return;
        const float4 v = src[i];
        uint32_t h0, l0, h1, l1;
        pack2(v.x, v.y, h0, l0);
        pack2(v.z, v.w, h1, l1);
        hi[i] = make_uint2(h0, h1);
        lo[i] = make_uint2(l0, l1);
        return;
    }

    // ---- adapter path: one output column per block ----
    const int abx = blockIdx.x - n4blk;            // 0..4095
    const int np = 2048 + abx;
    const float* wrow = Wfp + (long)np * KDIM;

    float part[AL_] = {};
    for (int k = threadIdx.x; k < KDIM; k += 256) {
        const float w = wrow[k];
        #pragma unroll
        for (int j = 0; j < AL_; j++) part[j] += w * emb[j*KDIM + k];
    }
    #pragma unroll
    for (int j = 0; j < AL_; j++)
        #pragma unroll
        for (int off = 16; off; off >>= 1)
            part[j] += __shfl_xor_sync(0xffffffffu, part[j], off);

    __shared__ float red[AL_][8];
    const int w = threadIdx.x >> 5, lane = threadIdx.x & 31;
    if (lane == 0)
        #pragma unroll
        for (int j = 0; j < AL_; j++) red[j][w] = part[j];
    __syncthreads();
    if (threadIdx.x < AL_) {
        const int j = threadIdx.x;
        float s = 0.f;
        #pragma unroll
        for (int ww = 0; ww < 8; ww++) s += red[j][ww];
        const int isv = abx >> 11;
        const int nn  = abx & 2047;
        const int h   = nn >> 7, d = nn & 127;
        float* dst = isv ? g_AV : g_AK;
        dst[(h*AL_ + j)*HS_ + d] = s;
    }
}

// ======================================================================
// split-bf16 x3 GEMM (NT): CTA 128x128, 4 warps of 64x64, KC=32,
// 3-stage cp.async pipeline, 2 CTAs/SM.  (round-9 exact)
// MODE 0: rope + pack -> g_{Q,K,V}{h,l}.   MODE 1: fp32 write to Cout.
// ======================================================================
#define KC 32
#define STAGE_B 32768
#define NSTAGE 3
#define GEMM_SMEM (NSTAGE*STAGE_B)   // 96 KB -> 2 CTAs/SM

template<int MODE>
__global__ __launch_bounds__(128, 2) void tgemm(
    const __nv_bfloat16* __restrict__ Ah, const __nv_bfloat16* __restrict__ Al,
    const __nv_bfloat16* __restrict__ Bh, const __nv_bfloat16* __restrict__ Bl,
    const float* __restrict__ rope, float* __restrict__ Cout)
{
    extern __shared__ __align__(1024) char smx[];
    const uint32_t sb = smem_u32(smx);

    const int tid  = threadIdx.x;
    const int wid  = tid >> 5;
    const int lane = tid & 31;
    const int wm   = wid & 1;
    const int wn   = wid >> 1;
    const int bm   = blockIdx.y << 7;
    const int bn   = blockIdx.x << 7;

    int lrow[4], lchk[4]; uint32_t lsw[4];
    #pragma unroll
    for (int f = 0; f < 4; f++) {
        int idx = tid + (f << 7);
        lrow[f] = idx >> 2; lchk[f] = idx & 3;
        lsw[f] = tswz(lrow[f], lchk[f]);
    }

    const int grp = lane >> 3, lr = lane & 7;
    uint32_t offA[4][2], offB[4][2];
    #pragma unroll
    for (int i = 0; i < 4; i++)
        #pragma unroll
        for (int ks = 0; ks < 2; ks++) {
            int row = wm*64 + i*16 + (grp & 1)*8 + lr;
            offA[i][ks] = tswz(row, (grp >> 1) + 2*ks);
        }
    #pragma unroll
    for (int jj = 0; jj < 4; jj++)
        #pragma unroll
        for (int ks = 0; ks < 2; ks++) {
            int row = wn*64 + jj*16 + (grp >> 1)*8 + lr;
            offB[jj][ks] = tswz(row, (grp & 1) + 2*ks);
        }

    float acc[4][8][4];
    #pragma unroll
    for (int i = 0; i < 4; i++)
        #pragma unroll
        for (int j = 0; j < 8; j++)
            #pragma unroll
            for (int c = 0; c < 4; c++) acc[i][j][c] = 0.f;

    const __nv_bfloat16* Abh = Ah + (long)bm * KDIM;
    const __nv_bfloat16* Abl = Al + (long)bm * KDIM;
    const __nv_bfloat16* Bbh = Bh + (long)bn * KDIM;
    const __nv_bfloat16* Bbl = Bl + (long)bn * KDIM;

    auto load_stage = [&](int c, int s) {
        const uint32_t st = sb + (uint32_t)s * STAGE_B;
        const long kb = (long)c * KC;
        #pragma unroll
        for (int f = 0; f < 4; f++) {
            const long ga = (long)lrow[f]*KDIM + kb + lchk[f]*8;
            CP_A16(st + 0*8192 + lsw[f], Abh + ga);
            CP_A16(st + 1*8192 + lsw[f], Abl + ga);
            CP_A16(st + 2*8192 + lsw[f], Bbh + ga);
            CP_A16(st + 3*8192 + lsw[f], Bbl + ga);
        }
        CP_COMMIT();
    };

    const int NCH = KDIM / KC;     // 64
    load_stage(0, 0);
    load_stage(1, 1);

    for (int c = 0; c < NCH; c++) {
        CP_WAIT(1);
        __syncthreads();

        const uint32_t stg = sb + (uint32_t)(c % NSTAGE) * STAGE_B;
        #pragma unroll
        for (int ks = 0; ks < 2; ks++) {
            uint32_t ah[4][4], al[4][4], bh[4][4], bl[4][4];
            #pragma unroll
            for (int i = 0; i < 4; i++) {
                LDSM_X4(ah[i], stg + 0*8192 + offA[i][ks]);
                LDSM_X4(al[i], stg + 1*8192 + offA[i][ks]);
            }
            #pragma unroll
            for (int jj = 0; jj < 4; jj++) {
                LDSM_X4(bh[jj], stg + 2*8192 + offB[jj][ks]);
                LDSM_X4(bl[jj], stg + 3*8192 + offB[jj][ks]);
            }
            #pragma unroll
            for (int i = 0; i < 4; i++)
                #pragma unroll
                for (int j = 0; j < 8; j++) {
                    const int jj = j >> 1, jo = (j & 1) << 1;
                    MMA_BF16(acc[i][j], ah[i], bh[jj][jo], bh[jj][jo+1]);
                    MMA_BF16(acc[i][j], ah[i], bl[jj][jo], bl[jj][jo+1]);
                    MMA_BF16(acc[i][j], al[i], bh[jj][jo], bh[jj][jo+1]);
                }
        }

        if (c + 2 < NCH) load_stage(c + 2, (c + 2) % NSTAGE);
        else CP_COMMIT();
    }

    // ---------------- epilogue ----------------
    const int lr4 = lane >> 2;
    const int lc2 = (lane & 3) << 1;

    if (MODE == 0) {
        const int sel = bn >> 11;
        const int hh  = (bn & 2047) >> 7;
        __nv_bfloat16* baseH = (sel == 0 ? g_Qh : (sel == 1 ? g_Kh : g_Vh));
        __nv_bfloat16* baseL = (sel == 0 ? g_Ql : (sel == 1 ? g_Kl : g_Vl));
        #pragma unroll
        for (int i = 0; i < 4; i++) {
            #pragma unroll
            for (int j = 0; j < 8; j++) {
                const int d = wn*64 + j*8 + lc2;
                #pragma unroll
                for (int rh = 0; rh < 2; rh++) {
                    const int m = bm + wm*64 + i*16 + lr4 + rh*8;
                    const int b = m >> 11, t = m & 2047;
                    float v0 = acc[i][j][rh*2], v1 = acc[i][j][rh*2+1];
                    if (sel < 2) {
                        const float2 rr = *(const float2*)(rope + (long)t*128 + d);
                        const float o0 = v0*rr.x - v1*rr.y;
                        const float o1 = v1*rr.x + v0*rr.y;
                        v0 = o0; v1 = o1;
                    }
                    uint32_t hi, lo; pack2(v0, v1, hi, lo);
                    const long idx = ((long)(b*H_ + hh)*T_ + t)*HS_ + d;
                    *(uint32_t*)((uint16_t*)baseH + idx) = hi;
                    *(uint32_t*)((uint16_t*)baseL + idx) = lo;
                }
            }
        }
    } else {
        #pragma unroll
        for (int i = 0; i < 4; i++)
            #pragma unroll
            for (int j = 0; j < 8; j++) {
                const int ncol = bn + wn*64 + j*8 + lc2;
                #pragma unroll
                for (int rh = 0; rh < 2; rh++) {
                    const int m = bm + wm*64 + i*16 + lr4 + rh*8;
                    *(float2*)(Cout + (long)m*C_ + ncol) =
                        make_float2(acc[i][j][rh*2], acc[i][j][rh*2+1]);
                }
            }
    }
}

// ======================================================================
// Flash attention (split-bf16 x3 tensor cores), cp.async loads of
// pre-split Q/K/V, 2-stage KV pipeline, fused adapter + gating.
// BM=128, BN=64, 8 warps.  (round-9 exact)
// ======================================================================
#define FQHI 0
#define FQLO 32768
#define FKV  65536
#define KVSTAGE_B 65536          // Kh,Kl,Vh,Vl x 16KB
#define FAK  (FKV + 2*KVSTAGE_B)             // 196608
#define FAV  (FAK + AL_*HS_*4)               // 201728
#define FLASH_SMEM (FAV + AL_*HS_*4)         // 206848

__global__ __launch_bounds__(256, 1) void flash_mma(const float* __restrict__ gating)
{
    extern __shared__ __align__(1024) char fsm[];
    const uint32_t sb = smem_u32(fsm);

    const int tid  = threadIdx.x;
    const int w    = tid >> 5;
    const int lane = tid & 31;
    const int grp  = lane >> 3, lr = lane & 7;
    const int lam  = lane & 3;
    const int rsub = lane >> 2;

    const int qb = (gridDim.x - 1) - blockIdx.x;
    const int bhI = blockIdx.y;
    const int h  = bhI & 15;
    const int b  = bhI >> 4;

    const __nv_bfloat16* Qhg = g_Qh + (long)bhI*T_*HS_ + (long)qb*128*HS_;
    const __nv_bfloat16* Qlg = g_Ql + (long)bhI*T_*HS_ + (long)qb*128*HS_;
    const __nv_bfloat16* Khg = g_Kh + (long)bhI*T_*HS_;
    const __nv_bfloat16* Klg = g_Kl + (long)bhI*T_*HS_;
    const __nv_bfloat16* Vhg = g_Vh + (long)bhI*T_*HS_;
    const __nv_bfloat16* Vlg = g_Vl + (long)bhI*T_*HS_;

    // ---- group 0: Q tiles (hi+lo) ----
    #pragma unroll
    for (int f = 0; f < 8; f++) {
        const int slot = tid + (f << 8);           // 0..2047
        const int row = slot >> 4, c8 = slot & 15;
        const uint32_t off = (uint32_t)((c8 >> 2) * 8192) + tswz(row, c8 & 3);
        const long g = (long)row*HS_ + c8*8;
        CP_A16(sb + FQHI + off, Qhg + g);
        CP_A16(sb + FQLO + off, Qlg + g);
    }
    CP_COMMIT();

    auto load_kv = [&](int kb) {
        const uint32_t st = sb + FKV + (uint32_t)(kb & 1) * KVSTAGE_B;
        const long gb = (long)kb*64*HS_;
        #pragma unroll
        for (int f = 0; f < 4; f++) {
            const int slot = tid + (f << 8);       // 0..1023
            const int row = slot >> 4, c8 = slot & 15;
            const uint32_t off = (uint32_t)((c8 >> 2) * 4096) + tswz(row, c8 & 3);
            const long g = gb + (long)row*HS_ + c8*8;
            CP_A16(st + 0     + off, Khg + g);
            CP_A16(st + 16384 + off, Klg + g);
            CP_A16(st + 32768 + off, Vhg + g);
            CP_A16(st + 49152 + off, Vlg + g);
        }
        CP_COMMIT();
    };

    // ---- adapter tiles (fp32, plain stores) ----
    {
        const float4* AKg = (const float4*)(g_AK + h*AL_*HS_);
        const float4* AVg = (const float4*)(g_AV + h*AL_*HS_);
        for (int i = tid; i < AL_*HS_/4; i += 256) {
            ((float4*)(fsm + FAK))[i] = AKg[i];
            ((float4*)(fsm + FAV))[i] = AVg[i];
        }
    }

    float O[16][4];
    #pragma unroll
    for (int nf = 0; nf < 16; nf++)
        #pragma unroll
        for (int c = 0; c < 4; c++) O[nf][c] = 0.f;
    float m0 = NEG_BIG, m1 = NEG_BIG, l0 = 0.f, l1 = 0.f;
    const float scale = 0.08838834764831843f;

    const int rowg0 = qb*128 + 16*w + rsub;
    const int warp_rmax = qb*128 + 16*w + 15;

    const int kmax = 2*qb + 2;
    load_kv(0);                                   // group 1

    for (int kb = 0; kb < kmax; kb++) {
        if (kb + 1 < kmax) load_kv(kb + 1);
        else CP_COMMIT();
        CP_WAIT(1);
        __syncthreads();

        if (kb*64 <= warp_rmax) {
            const uint32_t kvst = sb + FKV + (uint32_t)(kb & 1) * KVSTAGE_B;

            // ---- S = Q K^T ----
            float S[8][4];
            #pragma unroll
            for (int j = 0; j < 8; j++)
                #pragma unroll
                for (int c = 0; c < 4; c++) S[j][c] = 0.f;

            #pragma unroll
            for (int ks = 0; ks < 8; ks++) {
                const int tQ = ks >> 1, chb = (ks & 1) << 1;
                const int arow = 16*w + (grp & 1)*8 + lr;
                const uint32_t aoff = (uint32_t)(tQ*8192) + tswz(arow, chb + (grp >> 1));
                uint32_t ah[4], al[4];
                LDSM_X4(ah, sb + FQHI + aoff);
                LDSM_X4(al, sb + FQLO + aoff);
                #pragma unroll
                for (int jj = 0; jj < 4; jj++) {
                    const int brow = jj*16 + (grp >> 1)*8 + lr;
                    const uint32_t boff = (uint32_t)(tQ*4096) + tswz(brow, (grp & 1) + chb);
                    uint32_t kh[4], kl[4];
                    LDSM_X4(kh, kvst + 0     + boff);
                    LDSM_X4(kl, kvst + 16384 + boff);
                    #pragma unroll
                    for (int j2 = 0; j2 < 2; j2++) {
                        const int j = jj*2 + j2, jo = j2 << 1;
                        MMA_BF16(S[j], ah, kh[jo], kh[jo+1]);
                        MMA_BF16(S[j], ah, kl[jo], kl[jo+1]);
                        MMA_BF16(S[j], al, kh[jo], kh[jo+1]);
                    }
                }
            }

            // ---- scale + mask ----
            const bool needMask = (kb*64 + 63) > (qb*128 + 16*w);
            #pragma unroll
            for (int j = 0; j < 8; j++)
                #pragma unroll
                for (int c = 0; c < 4; c++) {
                    float sv = S[j][c] * scale;
                    if (needMask) {
                        const int colg = kb*64 + j*8 + 2*lam + (c & 1);
                        const int rowg = rowg0 + ((c >> 1) << 3);
                        if (colg > rowg) sv = NEG_BIG;
                    }
                    S[j][c] = sv;
                }

            // ---- online softmax ----
            float mx0 = S[0][0], mx1 = S[0][2];
            #pragma unroll
            for (int j = 0; j < 8; j++) {
                mx0 = fmaxf(mx0, fmaxf(S[j][0], S[j][1]));
                mx1 = fmaxf(mx1, fmaxf(S[j][2], S[j][3]));
            }
            mx0 = fmaxf(mx0, __shfl_xor_sync(0xffffffffu, mx0, 1));
            mx0 = fmaxf(mx0, __shfl_xor_sync(0xffffffffu, mx0, 2));
            mx1 = fmaxf(mx1, __shfl_xor_sync(0xffffffffu, mx1, 1));
            mx1 = fmaxf(mx1, __shfl_xor_sync(0xffffffffu, mx1, 2));
            const float mn0 = fmaxf(m0, mx0);
            const float mn1 = fmaxf(m1, mx1);
            const float corr0 = __expf(m0 - mn0);
            const float corr1 = __expf(m1 - mn1);
            float rs0 = 0.f, rs1 = 0.f;
            #pragma unroll
            for (int j = 0; j < 8; j++) {
                S[j][0] = __expf(S[j][0] - mn0);
                S[j][1] = __expf(S[j][1] - mn0);
                S[j][2] = __expf(S[j][2] - mn1);
                S[j][3] = __expf(S[j][3] - mn1);
                rs0 += S[j][0] + S[j][1];
                rs1 += S[j][2] + S[j][3];
            }
            l0 = l0*corr0 + rs0;
            l1 = l1*corr1 + rs1;
            m0 = mn0; m1 = mn1;
            #pragma unroll
            for (int nf = 0; nf < 16; nf++) {
                O[nf][0] *= corr0; O[nf][1] *= corr0;
                O[nf][2] *= corr1; O[nf][3] *= corr1;
            }

            // ---- O += P V ----
            #pragma unroll
            for (int ks2 = 0; ks2 < 4; ks2++) {
                const int j0 = 2*ks2, j1 = j0 + 1;
                uint32_t phi[4], plo[4];
                pack2(S[j0][0], S[j0][1], phi[0], plo[0]);
                pack2(S[j0][2], S[j0][3], phi[1], plo[1]);
                pack2(S[j1][0], S[j1][1], phi[2], plo[2]);
                pack2(S[j1][2], S[j1][3], phi[3], plo[3]);
                #pragma unroll
                for (int nc = 0; nc < 8; nc++) {
                    const int vrow = ks2*16 + (grp & 1)*8 + lr;
                    const uint32_t voff = (uint32_t)((nc >> 1) * 4096)
                                        + tswz(vrow, ((nc & 1) << 1) + (grp >> 1));
                    uint32_t vh[4], vl[4];
                    LDSM_X4_T(vh, kvst + 32768 + voff);
                    LDSM_X4_T(vl, kvst + 49152 + voff);
                    MMA_BF16(O[2*nc],   phi, vh[0], vh[1]);
                    MMA_BF16(O[2*nc+1], phi, vh[2], vh[3]);
                    MMA_BF16(O[2*nc],   phi, vl[0], vl[1]);
                    MMA_BF16(O[2*nc+1], phi, vl[2], vl[3]);
                    MMA_BF16(O[2*nc],   plo, vh[0], vh[1]);
                    MMA_BF16(O[2*nc+1], plo, vh[2], vh[3]);
                }
            }
        }
        __syncthreads();
    }

    // ---- finalize l ----
    l0 += __shfl_xor_sync(0xffffffffu, l0, 1);
    l0 += __shfl_xor_sync(0xffffffffu, l0, 2);
    l1 += __shfl_xor_sync(0xffffffffu, l1, 1);
    l1 += __shfl_xor_sync(0xffffffffu, l1, 2);

    // ---- adapter attention (q = hi+lo from smem) ----
    float sa0[AL_], sa1[AL_];
    #pragma unroll
    for (int j = 0; j < AL_; j++) { sa0[j] = 0.f; sa1[j] = 0.f; }
    const float* AKs = (const float*)(fsm + FAK);
    const float* AVs = (const float*)(fsm + FAV);
    #pragma unroll
    for (int rr = 0; rr < 2; rr++) {
        const int rowL = 16*w + rsub + rr*8;
        float* sa = rr ? sa1 : sa0;
        #pragma unroll
        for (int ch = 0; ch < 4; ch++) {
            const uint32_t off = (uint32_t)(lam * 8192) + tswz(rowL, ch);
            uint4 qh = *(const uint4*)(fsm + FQHI + off);
            uint4 ql = *(const uint4*)(fsm + FQLO + off);
            const uint32_t* qhp = (const uint32_t*)&qh;
            const uint32_t* qlp = (const uint32_t*)&ql;
            float q[8];
            #pragma unroll
            for (int e = 0; e < 4; e++) {
                __nv_bfloat162 bh2 = *reinterpret_cast<const __nv_bfloat162*>(&qhp[e]);
                __nv_bfloat162 bl2 = *reinterpret_cast<const __nv_bfloat162*>(&qlp[e]);
                q[2*e]   = __low2float(bh2)  + __low2float(bl2);
                q[2*e+1] = __high2float(bh2) + __high2float(bl2);
            }
            const int d0 = lam*32 + ch*8;
            #pragma unroll
            for (int j = 0; j < AL_; j++) {
                const float* ak = AKs + j*HS_ + d0;
                #pragma unroll
                for (int e = 0; e < 8; e++) sa[j] += q[e] * ak[e];
            }
        }
    }
    #pragma unroll
    for (int j = 0; j < AL_; j++) {
        sa0[j] += __shfl_xor_sync(0xffffffffu, sa0[j], 1);
        sa0[j] += __shfl_xor_sync(0xffffffffu, sa0[j], 2);
        sa1[j] += __shfl_xor_sync(0xffffffffu, sa1[j], 1);
        sa1[j] += __shfl_xor_sync(0xffffffffu, sa1[j], 2);
    }

    const float g = gating[h];
    #pragma unroll
    for (int rr = 0; rr < 2; rr++) {
        float* sa = rr ? sa1 : sa0;
        const float li = rr ? l1 : l0;
        const int rowg = rowg0 + rr*8;
        float mx = sa[0]*scale;
        #pragma unroll
        for (int j = 1; j < AL_; j++) mx = fmaxf(mx, sa[j]*scale);
        float pa[AL_], ssum = 0.f;
        #pragma unroll
        for (int j = 0; j < AL_; j++) { pa[j] = __expf(sa[j]*scale - mx); ssum += pa[j]; }
        const float pg = g / ssum;
        const float inv_l = 1.f / li;
        const long yidx0 = ((long)b*T_ + rowg)*C_ + h*HS_;
        #pragma unroll
        for (int nf = 0; nf < 16; nf++) {
            const int d = nf*8 + 2*lam;
            float o0 = O[nf][rr*2]   * inv_l;
            float o1 = O[nf][rr*2+1] * inv_l;
            #pragma unroll
            for (int j = 0; j < AL_; j++) {
                const float p = pa[j] * pg;
                o0 += p * AVs[j*HS_ + d];
                o1 += p * AVs[j*HS_ + d + 1];
            }
            uint32_t hi, lo; pack2(o0, o1, hi, lo);
            *(uint32_t*)((uint16_t*)g_Yh + yidx0 + d) = hi;
            *(uint32_t*)((uint16_t*)g_Yl + yidx0 + d) = lo;
        }
    }
}

// ======================================================================
extern "C" void kernel_launch(void* const* d_in, const int* in_sizes, int n_in,
                              void* d_out, int out_size)
{
    const float* x      = (const float*)d_in[0];
    const float* rope   = (const float*)d_in[1];
    const float* W_attn = (const float*)d_in[3];
    const float* W_proj = (const float*)d_in[4];
    const float* emb    = (const float*)d_in[5];
    const float* gating = (const float*)d_in[6];
    float* out = (float*)d_out;

    void *xh, *xl, *wah, *wal, *wph, *wpl, *yh, *yl;
    cudaGetSymbolAddress(&xh,  g_xh);  cudaGetSymbolAddress(&xl,  g_xl);
    cudaGetSymbolAddress(&wah, g_wah); cudaGetSymbolAddress(&wal, g_wal);
    cudaGetSymbolAddress(&wph, g_wph); cudaGetSymbolAddress(&wpl, g_wpl);
    cudaGetSymbolAddress(&yh,  g_Yh);  cudaGetSymbolAddress(&yl,  g_Yl);

    cudaFuncSetAttribute(tgemm<0>, cudaFuncAttributeMaxDynamicSharedMemorySize, GEMM_SMEM);
    cudaFuncSetAttribute(tgemm<1>, cudaFuncAttributeMaxDynamicSharedMemorySize, GEMM_SMEM);
    cudaFuncSetAttribute(flash_mma, cudaFuncAttributeMaxDynamicSharedMemorySize, FLASH_SMEM);

    // 0) split inputs into bf16 hi/lo; adapter K/V fused into the W_attn
    //    split launch as extra (cheap) blocks
    {
        int n4;
        n4 = M_ROWS*KDIM/4;
        conv_split<<<(n4+255)/256, 256>>>((const float4*)x, (uint2*)xh, (uint2*)xl, n4);
        n4 = 3*C_*KDIM/4;
        const int n4blk = (n4 + 255) / 256;
        conv_split_wa<<<n4blk + 4096, 256>>>(
            (const float4*)W_attn, (uint2*)wah, (uint2*)wal, n4, W_attn, emb);
        n4 = C_*KDIM/4;
        conv_split<<<(n4+255)/256, 256>>>((const float4*)W_proj, (uint2*)wph, (uint2*)wpl, n4);
    }
    // 1) QKV GEMM + rope -> split Q/K/V
    tgemm<0><<<dim3(48, 32), 128, GEMM_SMEM>>>(
        (const __nv_bfloat16*)xh, (const __nv_bfloat16*)xl,
        (const __nv_bfloat16*)wah, (const __nv_bfloat16*)wal, rope, nullptr);
    // 2) flash attention + fused adapter/gating -> split Y
    flash_mma<<<dim3(T_/128, B_*H_), 256, FLASH_SMEM>>>(gating);
    // 3) output projection -> fp32 out
    tgemm<1><<<dim3(16, 32), 128, GEMM_SMEM>>>(
        (const __nv_bfloat16*)yh, (const __nv_bfloat16*)yl,
        (const __nv_bfloat16*)wph, (const __nv_bfloat16*)wpl, nullptr, out);
}